// round 13
// baseline (speedup 1.0000x reference)
#include <cuda_runtime.h>

// Ragged segment mean, uniform-chunk fused kernel (R10: CHUNK=32 + fast path):
//   Row range [s,e) of batch b cut into contiguous CHUNK=32-row chunks.
//   CTAs with c >= ceil(len/32) exit instantly.  nchunks==1 rows take a
//   direct-write fast path (no partial/atomic).  Otherwise the last-done
//   CTA (acq_rel counter) sums the OTHER chunks' partials (its own is still
//   in registers), divides, writes out[b], discards the dirty partial lines
//   from L2 (no DRAM writeback), resets the counter.
//
// seq: [B=2048, L=512, D=512] fp32, begin/end: [B] int32, out: [B, D] fp32.

#define B_DIM 2048
#define L_DIM 512
#define D_DIM 512
#define D_VEC (D_DIM / 4)     // 128 float4 per row
#define CHUNK 32              // rows per chunk
#define MAXC  8               // max chunks per b (len <= 256)

__device__ float g_partial[(size_t)B_DIM * MAXC * D_DIM];
__device__ int   g_count[B_DIM];   // zero-initialized at load; reset each call

__device__ __forceinline__ int atomic_add_acq_rel(int* addr, int val) {
    int old;
    asm volatile("atom.add.acq_rel.gpu.global.s32 %0, [%1], %2;"
                 : "=r"(old) : "l"(addr), "r"(val) : "memory");
    return old;
}

__device__ __forceinline__ void l2_discard_128(const void* p) {
    asm volatile("discard.global.L2 [%0], 128;" :: "l"(p) : "memory");
}

__global__ __launch_bounds__(D_VEC, 16)
void ragged_mean_chunk_kernel(const float* __restrict__ seq,
                              const int* __restrict__ begin,
                              const int* __restrict__ end,
                              float* __restrict__ out) {
    const int c   = blockIdx.x;            // chunk index 0..MAXC-1
    const int b   = blockIdx.y;
    const int tid = threadIdx.x;           // 0..127 -> float4 column

    const int s   = __ldg(begin + b);
    const int e   = __ldg(end + b);
    const int len = e - s;
    const int nchunks = (len + CHUNK - 1) / CHUNK;

    if (c >= nchunks) return;              // empty chunk: retire instantly

    const int t0 = s + c * CHUNK;
    const int t1 = min(t0 + CHUNK, e);

    const float4* __restrict__ base =
        reinterpret_cast<const float4*>(seq) + (size_t)b * (L_DIM * D_VEC) + tid;

    float4 a = make_float4(0.f, 0.f, 0.f, 0.f);

    int t = t0;
    // Contiguous rows, x4 unrolled: 4 independent streaming LDG.128.
    for (; t + 4 <= t1; t += 4) {
        float4 v0 = __ldcs(base + (size_t)(t + 0) * D_VEC);
        float4 v1 = __ldcs(base + (size_t)(t + 1) * D_VEC);
        float4 v2 = __ldcs(base + (size_t)(t + 2) * D_VEC);
        float4 v3 = __ldcs(base + (size_t)(t + 3) * D_VEC);
        a.x += (v0.x + v1.x) + (v2.x + v3.x);
        a.y += (v0.y + v1.y) + (v2.y + v3.y);
        a.z += (v0.z + v1.z) + (v2.z + v3.z);
        a.w += (v0.w + v1.w) + (v2.w + v3.w);
    }
    for (; t < t1; ++t) {
        float4 v = __ldcs(base + (size_t)t * D_VEC);
        a.x += v.x; a.y += v.y; a.z += v.z; a.w += v.w;
    }

    // Fast path: single-chunk row -> write the mean directly, no partials.
    if (nchunks == 1) {
        const float inv = 1.0f / (float)len;
        float4 o;
        o.x = a.x * inv; o.y = a.y * inv; o.z = a.z * inv; o.w = a.w * inv;
        reinterpret_cast<float4*>(out)[(size_t)b * D_VEC + tid] = o;
        return;
    }

    float4* part = reinterpret_cast<float4*>(g_partial) + (size_t)b * MAXC * D_VEC;
    part[(size_t)c * D_VEC + tid] = a;

    __shared__ int is_last;
    __syncthreads();                        // all partial STGs issued
    if (tid == 0) {
        int prev = atomic_add_acq_rel(&g_count[b], 1);
        is_last = (prev == nchunks - 1);
    }
    __syncthreads();

    if (is_last) {
        // Our own chunk's sum is still in `a`; add only the other partials.
        float4 acc = a;
        for (int i = 0; i < nchunks; ++i) {
            if (i == c) continue;
            float4 p = part[(size_t)i * D_VEC + tid];
            acc.x += p.x; acc.y += p.y; acc.z += p.z; acc.w += p.w;
        }

        const float inv = 1.0f / (float)len;
        float4 o;
        o.x = acc.x * inv; o.y = acc.y * inv;
        o.z = acc.z * inv; o.w = acc.w * inv;

        reinterpret_cast<float4*>(out)[(size_t)b * D_VEC + tid] = o;

        // Drop the dirty partial lines from L2 (no DRAM writeback).
        __syncthreads();
        const char* pbytes = reinterpret_cast<const char*>(part);
        const int nlines = nchunks * (D_DIM * 4 / 128);   // 16 lines per chunk
        for (int l = tid; l < nlines; l += D_VEC)
            l2_discard_128(pbytes + (size_t)l * 128);

        if (tid == 0) g_count[b] = 0;   // reset for next graph replay
    }
}

extern "C" void kernel_launch(void* const* d_in, const int* in_sizes, int n_in,
                              void* d_out, int out_size) {
    const float* seq   = (const float*)d_in[0];
    const int*   begin = (const int*)d_in[1];
    const int*   endp  = (const int*)d_in[2];
    float*       out   = (float*)d_out;

    dim3 grid(MAXC, B_DIM);
    ragged_mean_chunk_kernel<<<grid, D_VEC>>>(seq, begin, endp, out);
}

// round 14
// speedup vs baseline: 1.0015x; 1.0015x over previous
#include <cuda_runtime.h>

// Ragged segment mean, uniform-chunk fused kernel (R13: deep-MLP full chunks):
//   CHUNK=32 contiguous rows per CTA.  Full chunks (the common case) run a
//   fully-unrolled 8-loads-per-group pipeline so ptxas front-batches up to
//   8 LDG.128 per thread (2x the in-flight loads of prior rounds).  Remainder
//   chunks use the generic x4 loop.  nchunks==1 rows write out directly.
//   Last-done CTA (acq_rel counter) adds the other chunks' partials (own sum
//   still in registers), divides, writes out[b], discards the dirty partial
//   lines from L2 (no DRAM writeback), resets the counter.
//
// seq: [B=2048, L=512, D=512] fp32, begin/end: [B] int32, out: [B, D] fp32.

#define B_DIM 2048
#define L_DIM 512
#define D_DIM 512
#define D_VEC (D_DIM / 4)     // 128 float4 per row
#define CHUNK 32              // rows per chunk
#define MAXC  8               // max chunks per b (len <= 256)

__device__ float g_partial[(size_t)B_DIM * MAXC * D_DIM];
__device__ int   g_count[B_DIM];   // zero-initialized at load; reset each call

__device__ __forceinline__ int atomic_add_acq_rel(int* addr, int val) {
    int old;
    asm volatile("atom.add.acq_rel.gpu.global.s32 %0, [%1], %2;"
                 : "=r"(old) : "l"(addr), "r"(val) : "memory");
    return old;
}

__device__ __forceinline__ void l2_discard_128(const void* p) {
    asm volatile("discard.global.L2 [%0], 128;" :: "l"(p) : "memory");
}

__global__ __launch_bounds__(D_VEC, 12)
void ragged_mean_chunk_kernel(const float* __restrict__ seq,
                              const int* __restrict__ begin,
                              const int* __restrict__ end,
                              float* __restrict__ out) {
    const int c   = blockIdx.x;            // chunk index 0..MAXC-1
    const int b   = blockIdx.y;
    const int tid = threadIdx.x;           // 0..127 -> float4 column

    const int s   = __ldg(begin + b);
    const int e   = __ldg(end + b);
    const int len = e - s;
    const int nchunks = (len + CHUNK - 1) / CHUNK;

    if (c >= nchunks) return;              // empty chunk: retire instantly

    const int t0 = s + c * CHUNK;
    const int t1 = min(t0 + CHUNK, e);

    const float4* __restrict__ base =
        reinterpret_cast<const float4*>(seq) + (size_t)b * (L_DIM * D_VEC) + tid;

    float4 a;

    if (t1 - t0 == CHUNK) {
        // Full chunk: fully unrolled, 8 independent streaming LDG.128 per
        // group -> deep MLP, loads front-batched by ptxas.
        float4 a0 = make_float4(0.f, 0.f, 0.f, 0.f);
        float4 a1 = make_float4(0.f, 0.f, 0.f, 0.f);
        const float4* p = base + (size_t)t0 * D_VEC;
        #pragma unroll
        for (int i = 0; i < CHUNK; i += 8) {
            float4 v0 = __ldcs(p + (size_t)(i + 0) * D_VEC);
            float4 v1 = __ldcs(p + (size_t)(i + 1) * D_VEC);
            float4 v2 = __ldcs(p + (size_t)(i + 2) * D_VEC);
            float4 v3 = __ldcs(p + (size_t)(i + 3) * D_VEC);
            float4 v4 = __ldcs(p + (size_t)(i + 4) * D_VEC);
            float4 v5 = __ldcs(p + (size_t)(i + 5) * D_VEC);
            float4 v6 = __ldcs(p + (size_t)(i + 6) * D_VEC);
            float4 v7 = __ldcs(p + (size_t)(i + 7) * D_VEC);
            a0.x += (v0.x + v1.x) + (v2.x + v3.x);
            a0.y += (v0.y + v1.y) + (v2.y + v3.y);
            a0.z += (v0.z + v1.z) + (v2.z + v3.z);
            a0.w += (v0.w + v1.w) + (v2.w + v3.w);
            a1.x += (v4.x + v5.x) + (v6.x + v7.x);
            a1.y += (v4.y + v5.y) + (v6.y + v7.y);
            a1.z += (v4.z + v5.z) + (v6.z + v7.z);
            a1.w += (v4.w + v5.w) + (v6.w + v7.w);
        }
        a = make_float4(a0.x + a1.x, a0.y + a1.y, a0.z + a1.z, a0.w + a1.w);
    } else {
        // Remainder chunk: generic x4 loop + scalar tail.
        a = make_float4(0.f, 0.f, 0.f, 0.f);
        int t = t0;
        for (; t + 4 <= t1; t += 4) {
            float4 v0 = __ldcs(base + (size_t)(t + 0) * D_VEC);
            float4 v1 = __ldcs(base + (size_t)(t + 1) * D_VEC);
            float4 v2 = __ldcs(base + (size_t)(t + 2) * D_VEC);
            float4 v3 = __ldcs(base + (size_t)(t + 3) * D_VEC);
            a.x += (v0.x + v1.x) + (v2.x + v3.x);
            a.y += (v0.y + v1.y) + (v2.y + v3.y);
            a.z += (v0.z + v1.z) + (v2.z + v3.z);
            a.w += (v0.w + v1.w) + (v2.w + v3.w);
        }
        for (; t < t1; ++t) {
            float4 v = __ldcs(base + (size_t)t * D_VEC);
            a.x += v.x; a.y += v.y; a.z += v.z; a.w += v.w;
        }
    }

    // Fast path: single-chunk row -> write the mean directly, no partials.
    if (nchunks == 1) {
        const float inv = 1.0f / (float)len;
        float4 o;
        o.x = a.x * inv; o.y = a.y * inv; o.z = a.z * inv; o.w = a.w * inv;
        reinterpret_cast<float4*>(out)[(size_t)b * D_VEC + tid] = o;
        return;
    }

    float4* part = reinterpret_cast<float4*>(g_partial) + (size_t)b * MAXC * D_VEC;
    part[(size_t)c * D_VEC + tid] = a;

    __shared__ int is_last;
    __syncthreads();                        // all partial STGs issued
    if (tid == 0) {
        int prev = atomic_add_acq_rel(&g_count[b], 1);
        is_last = (prev == nchunks - 1);
    }
    __syncthreads();

    if (is_last) {
        // Our own chunk's sum is still in `a`; add only the other partials.
        float4 acc = a;
        for (int i = 0; i < nchunks; ++i) {
            if (i == c) continue;
            float4 p = part[(size_t)i * D_VEC + tid];
            acc.x += p.x; acc.y += p.y; acc.z += p.z; acc.w += p.w;
        }

        const float inv = 1.0f / (float)len;
        float4 o;
        o.x = acc.x * inv; o.y = acc.y * inv;
        o.z = acc.z * inv; o.w = acc.w * inv;

        reinterpret_cast<float4*>(out)[(size_t)b * D_VEC + tid] = o;

        // Drop the dirty partial lines from L2 (no DRAM writeback).
        __syncthreads();
        const char* pbytes = reinterpret_cast<const char*>(part);
        const int nlines = nchunks * (D_DIM * 4 / 128);   // 16 lines per chunk
        for (int l = tid; l < nlines; l += D_VEC)
            l2_discard_128(pbytes + (size_t)l * 128);

        if (tid == 0) g_count[b] = 0;   // reset for next graph replay
    }
}

extern "C" void kernel_launch(void* const* d_in, const int* in_sizes, int n_in,
                              void* d_out, int out_size) {
    const float* seq   = (const float*)d_in[0];
    const int*   begin = (const int*)d_in[1];
    const int*   endp  = (const int*)d_in[2];
    float*       out   = (float*)d_out;

    dim3 grid(MAXC, B_DIM);
    ragged_mean_chunk_kernel<<<grid, D_VEC>>>(seq, begin, endp, out);
}